// round 6
// baseline (speedup 1.0000x reference)
#include <cuda_runtime.h>
#include <cstdint>

#define NN   1024
#define XD   128
#define HID  256
#define HP   128   // h-pairs

typedef unsigned long long u64;

// ---------------- scratch (device globals; no allocations) ----------------
__device__ float g_hxbT[HP * NN * 2];   // hx + b1, transposed, pair-interleaved [hp][n]{2}
__device__ float g_hyT [HP * NN * 2];   // hy, same layout
__device__ float g_c[NN];               // c_i = sum_h hy[i,h]*w2[h]
__device__ float g_d[NN];               // d_j = sum_h (hx[j,h]+b1[h])*w2[h]
__device__ float g_part[NN * 16];       // per (i, j-block) sum of exp(logit)
__device__ float g_diag[NN];            // T0_i = softplus(logit_ii)
__device__ int   g_ctr;

// ---------------- packed add helper: (r0,r1) = (a0+b0, a1+b1) -------------
__device__ __forceinline__ void fadd2(float& r0, float& r1,
                                      float a0, float a1, float b0, float b1) {
    asm("{\n\t"
        ".reg .b64 ra, rb, rc;\n\t"
        "mov.b64 ra, {%2, %3};\n\t"
        "mov.b64 rb, {%4, %5};\n\t"
        "add.rn.f32x2 rc, ra, rb;\n\t"
        "mov.b64 {%0, %1}, rc;\n\t"
        "}" : "=f"(r0), "=f"(r1) : "f"(a0), "f"(a1), "f"(b0), "f"(b1));
}

// ---------------- Kernel 1: h-projections ----------------
// z=0: g_hxbT = x@Wx + b1 ; z=1: g_hyT = y@Wy
// Block: 32n x 64h, 128 threads. A staged COALESCED then transposed in smem
// (single barrier). W read via uniform LDG.128 (L1-resident). Grid (32,4,2)=256.
__global__ __launch_bounds__(128) void gemm_h(const float* __restrict__ X,
                                              const float* __restrict__ Y,
                                              const float* __restrict__ W1,
                                              const float* __restrict__ b1) {
    const int z = blockIdx.z;
    const float* A = (z == 0) ? X : Y;
    const float* W = W1 + z * XD * HID;
    float* outT    = (z == 0) ? g_hxbT : g_hyT;

    __shared__ float s_aT[XD][33];   // [k][n], pitch 33 (conflict-free reads)

    const int tid = threadIdx.x;
    const int gn0 = blockIdx.x * 32;
    const int gh0 = blockIdx.y * 64;

    // Coalesced A load + smem transpose: f4 index = n*32 + k4
    #pragma unroll
    for (int r = 0; r < 8; r++) {
        int idx = tid + r * 128;
        int k4 = idx & 31, n_l = idx >> 5;
        float4 v = *(const float4*)(A + (gn0 + n_l) * XD + 4 * k4);
        s_aT[4 * k4 + 0][n_l] = v.x;
        s_aT[4 * k4 + 1][n_l] = v.y;
        s_aT[4 * k4 + 2][n_l] = v.z;
        s_aT[4 * k4 + 3][n_l] = v.w;
    }
    __syncthreads();

    const int n  = tid & 31;          // lane -> n (conflict-free LDS)
    const int hg = tid >> 5;          // warp -> 16-h group
    const float* Wp = W + gh0 + hg * 16;

    float acc[16];
    #pragma unroll
    for (int c = 0; c < 16; c++) acc[c] = 0.0f;

    #pragma unroll 4
    for (int k = 0; k < XD; k++) {
        float a = s_aT[k][n];
        const float* wk = Wp + k * HID;
        float4 w0 = *(const float4*)(wk + 0);
        float4 w1 = *(const float4*)(wk + 4);
        float4 w2_ = *(const float4*)(wk + 8);
        float4 w3 = *(const float4*)(wk + 12);
        acc[0]  = fmaf(a, w0.x, acc[0]);   acc[1]  = fmaf(a, w0.y, acc[1]);
        acc[2]  = fmaf(a, w0.z, acc[2]);   acc[3]  = fmaf(a, w0.w, acc[3]);
        acc[4]  = fmaf(a, w1.x, acc[4]);   acc[5]  = fmaf(a, w1.y, acc[5]);
        acc[6]  = fmaf(a, w1.z, acc[6]);   acc[7]  = fmaf(a, w1.w, acc[7]);
        acc[8]  = fmaf(a, w2_.x, acc[8]);  acc[9]  = fmaf(a, w2_.y, acc[9]);
        acc[10] = fmaf(a, w2_.z, acc[10]); acc[11] = fmaf(a, w2_.w, acc[11]);
        acc[12] = fmaf(a, w3.x, acc[12]);  acc[13] = fmaf(a, w3.y, acc[13]);
        acc[14] = fmaf(a, w3.z, acc[14]);  acc[15] = fmaf(a, w3.w, acc[15]);
    }

    // write pair-interleaved transposed output (+b1 for z==0), STG.64 coalesced
    #pragma unroll
    for (int c = 0; c < 16; c += 2) {
        int h = gh0 + hg * 16 + c;
        float v0 = acc[c], v1 = acc[c + 1];
        if (z == 0) { v0 += b1[h]; v1 += b1[h + 1]; }
        *(float2*)&outT[((h >> 1) * NN + gn0 + n) * 2] = make_float2(v0, v1);
    }
}

// ---------------- Kernel 2: c_i, d_j rank-1 terms (h split in 2) ----------
__global__ __launch_bounds__(256) void cd_kernel(const float* __restrict__ W2) {
    __shared__ float sc[256], sd[256];
    const int tid = threadIdx.x;
    const int i = blockIdx.x * 128 + (tid & 127);
    const int half = tid >> 7;
    const float2* hy = (const float2*)g_hyT;
    const float2* hx = (const float2*)g_hxbT;
    const float2* w2 = (const float2*)W2;
    float c = 0.0f, d = 0.0f;
    const int hp0 = half * 64;
    #pragma unroll 8
    for (int hp = hp0; hp < hp0 + 64; hp++) {
        float2 w = w2[hp];
        float2 a = hy[hp * NN + i];
        float2 b = hx[hp * NN + i];
        c = fmaf(a.x, w.x, fmaf(a.y, w.y, c));
        d = fmaf(b.x, w.x, fmaf(b.y, w.y, d));
    }
    sc[tid] = c; sd[tid] = d;
    __syncthreads();
    if (tid < 128) {
        g_c[i] = sc[tid] + sc[tid + 128];
        g_d[i] = sd[tid] + sd[tid + 128];
    }
}

// ---------------- Kernel 3: N^2 pair kernel + fused final reduction -------
// logit[i,j] = 0.5*(sum_h |hy[i,h]+hxb[j,h]|*w2[h] + c_i + d_j) + b2
// lse_i = log(1024 + sum_j e^logit)
// Tile 32i x 64j, 256 thr, scalar float accs; inner: add.f32x2 + FFMA(|z|).
__global__ __launch_bounds__(256, 4) void pair_kernel(const float* __restrict__ W2,
                                                      const float* __restrict__ b2,
                                                      float* __restrict__ out) {
    __shared__ float s_a[32][36];   // [i][h-chunk 32], pitch 144B
    __shared__ float s_b[64][36];   // [j][h-chunk 32]
    __shared__ float s_w[HID];
    __shared__ bool  s_last;
    __shared__ float s_red[16];

    const int tid  = threadIdx.x;
    const int lane = tid & 31, w = tid >> 5;   // 8 warps; warp -> 4 i rows
    const int i0 = blockIdx.y * 32;
    const int j0 = blockIdx.x * 64;
    const u64* hyp = (const u64*)g_hyT;
    const u64* hxp = (const u64*)g_hxbT;

    s_w[tid] = W2[tid];                        // 256 threads == HID

    float acc[4][2];
    #pragma unroll
    for (int a = 0; a < 4; a++) { acc[a][0] = 0.0f; acc[a][1] = 0.0f; }

    for (int ch = 0; ch < 8; ch++) {           // 32 h (16 hp) per chunk
        const int hp0 = ch * 16;
        __syncthreads();                       // covers s_w on first iter
        #pragma unroll
        for (int r = 0; r < 2; r++) {          // s_a: 32i x 16hp u64
            int idx = tid + r * 256;
            int i_l = idx & 31, hp_l = idx >> 5;
            *(u64*)&s_a[i_l][2 * hp_l] = hyp[(hp0 + hp_l) * NN + i0 + i_l];
        }
        #pragma unroll
        for (int r = 0; r < 4; r++) {          // s_b: 64j x 16hp u64
            int idx = tid + r * 256;
            int j_l = idx & 63, hp_l = idx >> 6;
            *(u64*)&s_b[j_l][2 * hp_l] = hxp[(hp0 + hp_l) * NN + j0 + j_l];
        }
        __syncthreads();

        #pragma unroll
        for (int st = 0; st < 8; st++) {       // 4 h per step
            float4 wv = *(const float4*)&s_w[ch * 32 + st * 4];
            float4 b0 = *(const float4*)&s_b[lane][st * 4];
            float4 b1 = *(const float4*)&s_b[lane + 32][st * 4];
            #pragma unroll
            for (int ii = 0; ii < 4; ii++) {
                float4 av = *(const float4*)&s_a[w * 4 + ii][st * 4];
                float z0, z1;
                fadd2(z0, z1, av.x, av.y, b0.x, b0.y);
                acc[ii][0] = fmaf(fabsf(z0), wv.x, acc[ii][0]);
                acc[ii][0] = fmaf(fabsf(z1), wv.y, acc[ii][0]);
                fadd2(z0, z1, av.z, av.w, b0.z, b0.w);
                acc[ii][0] = fmaf(fabsf(z0), wv.z, acc[ii][0]);
                acc[ii][0] = fmaf(fabsf(z1), wv.w, acc[ii][0]);
                fadd2(z0, z1, av.x, av.y, b1.x, b1.y);
                acc[ii][1] = fmaf(fabsf(z0), wv.x, acc[ii][1]);
                acc[ii][1] = fmaf(fabsf(z1), wv.y, acc[ii][1]);
                fadd2(z0, z1, av.z, av.w, b1.z, b1.w);
                acc[ii][1] = fmaf(fabsf(z0), wv.z, acc[ii][1]);
                acc[ii][1] = fmaf(fabsf(z1), wv.w, acc[ii][1]);
            }
        }
    }

    // ---- epilogue ----
    const float b2v = b2[0];
    const int gj0 = j0 + lane, gj1 = j0 + lane + 32;
    const float d0 = g_d[gj0], d1 = g_d[gj1];
    #pragma unroll
    for (int ii = 0; ii < 4; ii++) {
        const int gi = i0 + w * 4 + ii;
        const float ci = g_c[gi];
        float l0 = 0.5f * (acc[ii][0] + ci + d0) + b2v;
        float l1 = 0.5f * (acc[ii][1] + ci + d1) + b2v;
        float e = __expf(l0) + __expf(l1);
        if (gi == gj0) g_diag[gi] = fmaxf(l0, 0.0f) + log1pf(__expf(-fabsf(l0)));
        if (gi == gj1) g_diag[gi] = fmaxf(l1, 0.0f) + log1pf(__expf(-fabsf(l1)));
        e += __shfl_xor_sync(0xFFFFFFFFu, e, 16);
        e += __shfl_xor_sync(0xFFFFFFFFu, e, 8);
        e += __shfl_xor_sync(0xFFFFFFFFu, e, 4);
        e += __shfl_xor_sync(0xFFFFFFFFu, e, 2);
        e += __shfl_xor_sync(0xFFFFFFFFu, e, 1);
        if (lane == 0) g_part[gi * 16 + blockIdx.x] = e;
    }

    // ---- last block does the final reduction ----
    __threadfence();
    __syncthreads();
    if (tid == 0) {
        int old = atomicAdd(&g_ctr, 1);
        s_last = (old == 16 * 32 - 1);
    }
    __syncthreads();
    if (!s_last) return;
    __threadfence();

    float sumT0 = 0.0f, sumL = 0.0f;
    #pragma unroll
    for (int r = 0; r < 4; r++) {
        int i = tid * 4 + r;
        const float4* p = (const float4*)&g_part[i * 16];
        float4 a = p[0], b = p[1], c = p[2], d = p[3];
        float s = ((a.x + a.y) + (a.z + a.w)) + ((b.x + b.y) + (b.z + b.w)) +
                  ((c.x + c.y) + (c.z + c.w)) + ((d.x + d.y) + (d.z + d.w));
        sumL  += __logf(1024.0f + s);
        sumT0 += g_diag[i];
    }
    #pragma unroll
    for (int dlt = 16; dlt >= 1; dlt >>= 1) {
        sumT0 += __shfl_xor_sync(0xFFFFFFFFu, sumT0, dlt);
        sumL  += __shfl_xor_sync(0xFFFFFFFFu, sumL,  dlt);
    }
    if (lane == 0) { s_red[w] = sumT0; s_red[8 + w] = sumL; }
    __syncthreads();
    if (tid == 0) {
        float t0 = 0.0f, l = 0.0f;
        #pragma unroll
        for (int q = 0; q < 8; q++) { t0 += s_red[q]; l += s_red[8 + q]; }
        const float invn = 1.0f / 1024.0f;
        out[0] = t0 * invn - (l * invn - logf(1024.0f));
        g_ctr = 0;
    }
}

// ---------------- launch ----------------
extern "C" void kernel_launch(void* const* d_in, const int* in_sizes, int n_in,
                              void* d_out, int out_size) {
    (void)in_sizes; (void)n_in; (void)out_size;
    const float* X  = (const float*)d_in[0];
    const float* Y  = (const float*)d_in[1];
    const float* W1 = (const float*)d_in[2];
    const float* b1 = (const float*)d_in[3];
    const float* W2 = (const float*)d_in[4];
    const float* b2 = (const float*)d_in[5];

    gemm_h   <<<dim3(32, 4, 2), 128>>>(X, Y, W1, b1);
    cd_kernel<<<8, 256>>>(W2);
    pair_kernel<<<dim3(16, 32), 256>>>(W2, b2, (float*)d_out);
}

// round 8
// speedup vs baseline: 1.1881x; 1.1881x over previous
#include <cuda_runtime.h>
#include <cstdint>

#define NN   1024
#define XD   128
#define HID  256
#define HP   128   // h-pairs

typedef unsigned long long u64;

// ---------------- scratch (device globals; no allocations) ----------------
__device__ float g_hxbT[HP * NN * 2];   // hx + b1, transposed, pair-interleaved [hp][n]{2}
__device__ float g_hyT [HP * NN * 2];   // hy, same layout
__device__ float g_c[NN];               // c_i = sum_h hy[i,h]*w2[h]
__device__ float g_d[NN];               // d_j = sum_h (hx[j,h]+b1[h])*w2[h]
__device__ float g_part[NN * 16];       // per (i, j-block) sum of exp(logit)
__device__ float g_diag[NN];            // T0_i = softplus(logit_ii)
__device__ int   g_ctr;

// ---------------- packed add helper: (r0,r1) = (a0+b0, a1+b1) -------------
__device__ __forceinline__ void fadd2(float& r0, float& r1,
                                      float a0, float a1, float b0, float b1) {
    asm("{\n\t"
        ".reg .b64 ra, rb, rc;\n\t"
        "mov.b64 ra, {%2, %3};\n\t"
        "mov.b64 rb, {%4, %5};\n\t"
        "add.rn.f32x2 rc, ra, rb;\n\t"
        "mov.b64 {%0, %1}, rc;\n\t"
        "}" : "=f"(r0), "=f"(r1) : "f"(a0), "f"(a1), "f"(b0), "f"(b1));
}

// ---------------- Kernel 1: h-projections ----------------
// z=0: g_hxbT = x@Wx + b1 ; z=1: g_hyT = y@Wy
// Tile 32n x 32h, 128 threads (2n x 4h per thread). A: coalesced LDG.128 +
// one-time smem transpose (full k), pitch 36 (EVEN -> aligned LDS.64 reads,
// conflict-free). W: smem chunks of 64 k (coalesced fill). Grid (32,8,2)=512.
__global__ __launch_bounds__(128) void gemm_h(const float* __restrict__ X,
                                              const float* __restrict__ Y,
                                              const float* __restrict__ W1,
                                              const float* __restrict__ b1) {
    const int z = blockIdx.z;
    const float* A = (z == 0) ? X : Y;
    const float* W = W1 + z * XD * HID;
    float* outT    = (z == 0) ? g_hxbT : g_hyT;

    __shared__ float s_aT[XD][36];   // [k][n], 32 n used, pitch 36 (even!)
    __shared__ float s_w[64][32];    // [k-chunk][h]

    const int tid = threadIdx.x;
    const int gn0 = blockIdx.x * 32;
    const int gh0 = blockIdx.y * 32;

    // Coalesced A load (32 rows x 32 float4) + transpose into s_aT
    #pragma unroll
    for (int r = 0; r < 8; r++) {
        int idx = tid + r * 128;
        int k4 = idx & 31, n_l = idx >> 5;
        float4 v = *(const float4*)(A + (gn0 + n_l) * XD + 4 * k4);
        s_aT[4 * k4 + 0][n_l] = v.x;
        s_aT[4 * k4 + 1][n_l] = v.y;
        s_aT[4 * k4 + 2][n_l] = v.z;
        s_aT[4 * k4 + 3][n_l] = v.w;
    }

    const int tx = tid & 15;        // 16 n-threads, 2 n each
    const int ty = tid >> 4;        // 8 h-threads, 4 h each

    float acc[4][2];
    #pragma unroll
    for (int a = 0; a < 4; a++) { acc[a][0] = 0.0f; acc[a][1] = 0.0f; }

    for (int kc = 0; kc < XD; kc += 64) {
        if (kc) __syncthreads();     // protect s_w from previous chunk's readers
        // fill s_w: 64k x 32h = 512 float4, coalesced (4 rows x 128B per warp)
        #pragma unroll
        for (int r = 0; r < 4; r++) {
            int idx = tid + r * 128;
            int h4 = idx & 7, k_l = idx >> 3;
            *(float4*)&s_w[k_l][4 * h4] =
                *(const float4*)(W + (kc + k_l) * HID + gh0 + 4 * h4);
        }
        __syncthreads();             // also covers s_aT fill on first chunk
        #pragma unroll 8
        for (int k = 0; k < 64; k++) {
            float2 a2 = *(const float2*)&s_aT[kc + k][2 * tx];
            float4 w4 = *(const float4*)&s_w[k][4 * ty];
            acc[0][0] = fmaf(w4.x, a2.x, acc[0][0]);
            acc[0][1] = fmaf(w4.x, a2.y, acc[0][1]);
            acc[1][0] = fmaf(w4.y, a2.x, acc[1][0]);
            acc[1][1] = fmaf(w4.y, a2.y, acc[1][1]);
            acc[2][0] = fmaf(w4.z, a2.x, acc[2][0]);
            acc[2][1] = fmaf(w4.z, a2.y, acc[2][1]);
            acc[3][0] = fmaf(w4.w, a2.x, acc[3][0]);
            acc[3][1] = fmaf(w4.w, a2.y, acc[3][1]);
        }
    }

    // write pair-interleaved transposed output (+b1 for z==0)
    #pragma unroll
    for (int hh = 0; hh < 4; hh += 2) {
        int h = gh0 + 4 * ty + hh;          // even h: (h, h+1) are a pair
        float bb0 = 0.0f, bb1 = 0.0f;
        if (z == 0) { bb0 = b1[h]; bb1 = b1[h + 1]; }
        #pragma unroll
        for (int nn = 0; nn < 2; nn++) {
            int n = gn0 + 2 * tx + nn;
            *(float2*)&outT[((h >> 1) * NN + n) * 2] =
                make_float2(acc[hh][nn] + bb0, acc[hh + 1][nn] + bb1);
        }
    }
}

// ---------------- Kernel 2: c_i, d_j rank-1 terms (h split in 2) ----------
__global__ __launch_bounds__(256) void cd_kernel(const float* __restrict__ W2) {
    __shared__ float sc[256], sd[256];
    const int tid = threadIdx.x;
    const int i = blockIdx.x * 128 + (tid & 127);
    const int half = tid >> 7;
    const float2* hy = (const float2*)g_hyT;
    const float2* hx = (const float2*)g_hxbT;
    const float2* w2 = (const float2*)W2;
    float c = 0.0f, d = 0.0f;
    const int hp0 = half * 64;
    #pragma unroll 8
    for (int hp = hp0; hp < hp0 + 64; hp++) {
        float2 w = w2[hp];
        float2 a = hy[hp * NN + i];
        float2 b = hx[hp * NN + i];
        c = fmaf(a.x, w.x, fmaf(a.y, w.y, c));
        d = fmaf(b.x, w.x, fmaf(b.y, w.y, d));
    }
    sc[tid] = c; sd[tid] = d;
    __syncthreads();
    if (tid < 128) {
        g_c[i] = sc[tid] + sc[tid + 128];
        g_d[i] = sd[tid] + sd[tid + 128];
    }
}

// ---------------- Kernel 3: N^2 pair kernel + fused final reduction -------
// logit[i,j] = 0.5*(sum_h |hy[i,h]+hxb[j,h]|*w2[h] + c_i + d_j) + b2
// lse_i = log(1024 + sum_j e^logit)
// Tile 32i x 64j, 256 thr, scalar float accs; inner: add.f32x2 + FFMA(|z|).
__global__ __launch_bounds__(256, 4) void pair_kernel(const float* __restrict__ W2,
                                                      const float* __restrict__ b2,
                                                      float* __restrict__ out) {
    __shared__ float s_a[32][36];   // [i][h-chunk 32], pitch 144B
    __shared__ float s_b[64][36];   // [j][h-chunk 32]
    __shared__ float s_w[HID];
    __shared__ bool  s_last;
    __shared__ float s_red[16];

    const int tid  = threadIdx.x;
    const int lane = tid & 31, w = tid >> 5;   // 8 warps; warp -> 4 i rows
    const int i0 = blockIdx.y * 32;
    const int j0 = blockIdx.x * 64;
    const u64* hyp = (const u64*)g_hyT;
    const u64* hxp = (const u64*)g_hxbT;

    s_w[tid] = W2[tid];                        // 256 threads == HID

    float acc[4][2];
    #pragma unroll
    for (int a = 0; a < 4; a++) { acc[a][0] = 0.0f; acc[a][1] = 0.0f; }

    for (int ch = 0; ch < 8; ch++) {           // 32 h (16 hp) per chunk
        const int hp0 = ch * 16;
        __syncthreads();                       // covers s_w on first iter
        #pragma unroll
        for (int r = 0; r < 2; r++) {          // s_a: 32i x 16hp u64
            int idx = tid + r * 256;
            int i_l = idx & 31, hp_l = idx >> 5;
            *(u64*)&s_a[i_l][2 * hp_l] = hyp[(hp0 + hp_l) * NN + i0 + i_l];
        }
        #pragma unroll
        for (int r = 0; r < 4; r++) {          // s_b: 64j x 16hp u64
            int idx = tid + r * 256;
            int j_l = idx & 63, hp_l = idx >> 6;
            *(u64*)&s_b[j_l][2 * hp_l] = hxp[(hp0 + hp_l) * NN + j0 + j_l];
        }
        __syncthreads();

        #pragma unroll
        for (int st = 0; st < 8; st++) {       // 4 h per step
            float4 wv = *(const float4*)&s_w[ch * 32 + st * 4];
            float4 b0 = *(const float4*)&s_b[lane][st * 4];
            float4 b1 = *(const float4*)&s_b[lane + 32][st * 4];
            #pragma unroll
            for (int ii = 0; ii < 4; ii++) {
                float4 av = *(const float4*)&s_a[w * 4 + ii][st * 4];
                float z0, z1;
                fadd2(z0, z1, av.x, av.y, b0.x, b0.y);
                acc[ii][0] = fmaf(fabsf(z0), wv.x, acc[ii][0]);
                acc[ii][0] = fmaf(fabsf(z1), wv.y, acc[ii][0]);
                fadd2(z0, z1, av.z, av.w, b0.z, b0.w);
                acc[ii][0] = fmaf(fabsf(z0), wv.z, acc[ii][0]);
                acc[ii][0] = fmaf(fabsf(z1), wv.w, acc[ii][0]);
                fadd2(z0, z1, av.x, av.y, b1.x, b1.y);
                acc[ii][1] = fmaf(fabsf(z0), wv.x, acc[ii][1]);
                acc[ii][1] = fmaf(fabsf(z1), wv.y, acc[ii][1]);
                fadd2(z0, z1, av.z, av.w, b1.z, b1.w);
                acc[ii][1] = fmaf(fabsf(z0), wv.z, acc[ii][1]);
                acc[ii][1] = fmaf(fabsf(z1), wv.w, acc[ii][1]);
            }
        }
    }

    // ---- epilogue ----
    const float b2v = b2[0];
    const int gj0 = j0 + lane, gj1 = j0 + lane + 32;
    const float d0 = g_d[gj0], d1 = g_d[gj1];
    #pragma unroll
    for (int ii = 0; ii < 4; ii++) {
        const int gi = i0 + w * 4 + ii;
        const float ci = g_c[gi];
        float l0 = 0.5f * (acc[ii][0] + ci + d0) + b2v;
        float l1 = 0.5f * (acc[ii][1] + ci + d1) + b2v;
        float e = __expf(l0) + __expf(l1);
        if (gi == gj0) g_diag[gi] = fmaxf(l0, 0.0f) + log1pf(__expf(-fabsf(l0)));
        if (gi == gj1) g_diag[gi] = fmaxf(l1, 0.0f) + log1pf(__expf(-fabsf(l1)));
        e += __shfl_xor_sync(0xFFFFFFFFu, e, 16);
        e += __shfl_xor_sync(0xFFFFFFFFu, e, 8);
        e += __shfl_xor_sync(0xFFFFFFFFu, e, 4);
        e += __shfl_xor_sync(0xFFFFFFFFu, e, 2);
        e += __shfl_xor_sync(0xFFFFFFFFu, e, 1);
        if (lane == 0) g_part[gi * 16 + blockIdx.x] = e;
    }

    // ---- last block does the final reduction ----
    __threadfence();
    __syncthreads();
    if (tid == 0) {
        int old = atomicAdd(&g_ctr, 1);
        s_last = (old == 16 * 32 - 1);
    }
    __syncthreads();
    if (!s_last) return;
    __threadfence();

    float sumT0 = 0.0f, sumL = 0.0f;
    #pragma unroll
    for (int r = 0; r < 4; r++) {
        int i = tid * 4 + r;
        const float4* p = (const float4*)&g_part[i * 16];
        float4 a = p[0], b = p[1], c = p[2], d = p[3];
        float s = ((a.x + a.y) + (a.z + a.w)) + ((b.x + b.y) + (b.z + b.w)) +
                  ((c.x + c.y) + (c.z + c.w)) + ((d.x + d.y) + (d.z + d.w));
        sumL  += __logf(1024.0f + s);
        sumT0 += g_diag[i];
    }
    #pragma unroll
    for (int dlt = 16; dlt >= 1; dlt >>= 1) {
        sumT0 += __shfl_xor_sync(0xFFFFFFFFu, sumT0, dlt);
        sumL  += __shfl_xor_sync(0xFFFFFFFFu, sumL,  dlt);
    }
    if (lane == 0) { s_red[w] = sumT0; s_red[8 + w] = sumL; }
    __syncthreads();
    if (tid == 0) {
        float t0 = 0.0f, l = 0.0f;
        #pragma unroll
        for (int q = 0; q < 8; q++) { t0 += s_red[q]; l += s_red[8 + q]; }
        const float invn = 1.0f / 1024.0f;
        out[0] = t0 * invn - (l * invn - logf(1024.0f));
        g_ctr = 0;
    }
}

// ---------------- launch ----------------
extern "C" void kernel_launch(void* const* d_in, const int* in_sizes, int n_in,
                              void* d_out, int out_size) {
    (void)in_sizes; (void)n_in; (void)out_size;
    const float* X  = (const float*)d_in[0];
    const float* Y  = (const float*)d_in[1];
    const float* W1 = (const float*)d_in[2];
    const float* b1 = (const float*)d_in[3];
    const float* W2 = (const float*)d_in[4];
    const float* b2 = (const float*)d_in[5];

    gemm_h   <<<dim3(32, 8, 2), 128>>>(X, Y, W1, b1);
    cd_kernel<<<8, 256>>>(W2);
    pair_kernel<<<dim3(16, 32), 256>>>(W2, b2, (float*)d_out);
}